// round 9
// baseline (speedup 1.0000x reference)
#include <cuda_runtime.h>
#include <cuda_fp16.h>
#include <cstdint>

#define B_SZ   4096
#define NN     256
#define NA     257
#define KP2H   65536        // W1t row length in halves: 256 i-blocks * 256
#define NSPLIT 8
#define NSLOT  8            // 8 mma splits (edge folded into the splits)

// ---------------- device-global scratch (no allocation allowed) ----------------
__device__ __align__(256) __half g_W1t[(size_t)NN * KP2H];          // 33.5 MB
__device__ __align__(256) __half g_W1e[(size_t)NN * 512];           // 256 KB edge weights
__device__ __align__(256) float g_aT [(size_t)256 * B_SZ];          // 4 MB
__device__ __align__(256) float g_bT [(size_t)256 * B_SZ];          // 4 MB
__device__ __align__(256) float g_part[(size_t)NSLOT * B_SZ * NN];  // 33.5 MB

// ---------------- helpers ----------------
static __device__ __forceinline__ uint32_t smem_u32(const void* p) {
    uint32_t a;
    asm("{ .reg .u64 t; cvta.to.shared.u64 t, %1; cvt.u32.u64 %0, t; }" : "=r"(a) : "l"(p));
    return a;
}
static __device__ __forceinline__ void cp16(uint32_t s, const void* g) {
    asm volatile("cp.async.cg.shared.global [%0], [%1], 16;" :: "r"(s), "l"(g));
}
// pack (lo,hi) fp32 -> f16x2 (single final rounding, RN)
static __device__ __forceinline__ uint32_t pkh2(float lo, float hi) {
    uint32_t r;
    asm("cvt.rn.f16x2.f32 %0, %1, %2;" : "=r"(r) : "f"(hi), "f"(lo));
    return r;
}
static __device__ __forceinline__ unsigned long long pk1(float x) {
    unsigned long long r;
    asm("mov.b64 %0, {%1, %1};" : "=l"(r) : "f"(x));
    return r;
}
static __device__ __forceinline__ unsigned long long ffma2(
    unsigned long long a, unsigned long long b, unsigned long long c) {
    unsigned long long d;
    asm("fma.rn.f32x2 %0, %1, %2, %3;" : "=l"(d) : "l"(a), "l"(b), "l"(c));
    return d;
}
static __device__ __forceinline__ void upk(unsigned long long v, float& x, float& y) {
    asm("mov.b64 {%0, %1}, %2;" : "=f"(x), "=f"(y) : "l"(v));
}
static __device__ __forceinline__ void ldsm4(uint32_t addr, uint32_t r[4]) {
    asm volatile("ldmatrix.sync.aligned.m8n8.x4.shared.b16 {%0,%1,%2,%3}, [%4];"
                 : "=r"(r[0]), "=r"(r[1]), "=r"(r[2]), "=r"(r[3]) : "r"(addr));
}
static __device__ __forceinline__ void mma_f16(
    float d[4], const uint32_t a[4], const uint32_t b[2]) {
    asm volatile(
        "mma.sync.aligned.m16n8k16.row.col.f32.f16.f16.f32 "
        "{%0,%1,%2,%3}, {%4,%5,%6,%7}, {%8,%9}, {%0,%1,%2,%3};"
        : "+f"(d[0]), "+f"(d[1]), "+f"(d[2]), "+f"(d[3])
        : "r"(a[0]), "r"(a[1]), "r"(a[2]), "r"(a[3]), "r"(b[0]), "r"(b[1]));
}

// ================================================================================
// Pre-pass 1: transpose inp1 / inp2  ->  g_aT / g_bT  (fp32)
// ================================================================================
__global__ void __launch_bounds__(256) prep_inputs(
    const float* __restrict__ in1, const float* __restrict__ in2) {
    __shared__ float tile[32 * 33];
    const float* src = blockIdx.z ? in2 : in1;
    float* dst = blockIdx.z ? g_bT : g_aT;
    const int m0 = blockIdx.x * 32, c0 = blockIdx.y * 32;
    const int c = threadIdx.x & 31, r0 = threadIdx.x >> 5;
#pragma unroll
    for (int q = 0; q < 4; q++) {
        int r = r0 + q * 8;
        tile[c * 33 + r] = src[(size_t)(m0 + r) * 256 + c0 + c];
    }
    __syncthreads();
#pragma unroll
    for (int q = 0; q < 4; q++) {
        int rr = r0 + q * 8;
        dst[(size_t)(c0 + rr) * B_SZ + m0 + c] = tile[rr * 33 + c];
    }
}

// ================================================================================
// Pre-pass 2: W1t[n][i*256 + j] = fp16(W1[i*257+j][n]),  i<256, j<256
// ================================================================================
__global__ void __launch_bounds__(256) prep_w1(const float* __restrict__ W1) {
    __shared__ float tile[32 * 33];
    const int i = blockIdx.x, j0 = blockIdx.y * 32, n0 = blockIdx.z * 32;
    const int c = threadIdx.x & 31, r0 = threadIdx.x >> 5;
#pragma unroll
    for (int q = 0; q < 4; q++) {
        int jr = r0 + q * 8;
        size_t k = (size_t)i * NA + j0 + jr;
        tile[c * 33 + jr] = W1[k * NN + n0 + c];
    }
    __syncthreads();
#pragma unroll
    for (int q = 0; q < 4; q++) {
        int nr = r0 + q * 8;
        g_W1t[(size_t)(n0 + nr) * KP2H + (size_t)i * 256 + j0 + c] =
            __float2half_rn(tile[nr * 33 + c]);
    }
}

// ================================================================================
// Pre-pass 3: edge weights. ke<257 -> W1 row ke*257+256 ; 257<=ke<512 -> row
// 65792+(ke-257).  g_W1e[n][ke] = fp16(W1[row(ke)][n]).
// ================================================================================
__global__ void __launch_bounds__(256) prep_w1e(const float* __restrict__ W1) {
    __shared__ float tile[32 * 33];
    const int k0 = blockIdx.x * 32, n0 = blockIdx.y * 32;
    const int c = threadIdx.x & 31, r0 = threadIdx.x >> 5;
#pragma unroll
    for (int q = 0; q < 4; q++) {
        int kr = r0 + q * 8;
        int ke = k0 + kr;
        size_t row = (ke < 257) ? ((size_t)ke * NA + 256)
                                : ((size_t)256 * NA + (ke - 257));
        tile[c * 33 + kr] = W1[row * NN + n0 + c];
    }
    __syncthreads();
#pragma unroll
    for (int q = 0; q < 4; q++) {
        int nr = r0 + q * 8;
        g_W1e[(size_t)(n0 + nr) * 512 + k0 + c] = __float2half_rn(tile[nr * 33 + c]);
    }
}

// ================================================================================
// Main: split-K implicit GEMM on mma.sync fp16 (m16n8k16).
// 256 threads = 8 warps (2 M-halves x 4 N-quarters), warp tile 64x32.
// b values staged in swizzled SMEM (fp32), refilled once per 32 tiles.
// grid (32 M, 2 N, 8 splits); tile 128 = 64 edge columns.
// SMEM: A0 A1 W0 W1 (16KB each) + bst 32KB = 96KB; 2 CTAs/SM.
// ================================================================================
__global__ void __launch_bounds__(256, 2) mma_main() {
    extern __shared__ __align__(1024) char smem[];
    const uint32_t sbase = smem_u32(smem);
    const uint32_t sA[2] = { sbase,         sbase + 16384 };
    const uint32_t sW[2] = { sbase + 32768, sbase + 49152 };
    const uint32_t sbst  = sbase + 65536;   // b-stage: 128 m x 64 k fp32, swizzled

    const int tid = threadIdx.x;
    const int L   = tid & 31;
    const int wid = tid >> 5;
    const int wm  = wid & 1;    // M half (64 rows)
    const int wn  = wid >> 1;   // N quarter (32 cols)
    const int m0  = blockIdx.x * 128;
    const int n0  = blockIdx.y * 128;
    const int sp  = blockIdx.z;
    const int i0  = sp * 32;

    // ldsm lane constants
    const int lsw  = L & 7;
    const int rowA = (L & 7) + ((L >> 3) & 1) * 8;
    const int hiA  = (L >> 4) & 1;
    const int rowB = (L & 7) + ((L >> 4) & 1) * 8;
    const int hiB  = (L >> 3) & 1;
    uint32_t swzA[4], swzB[4], aoff[4], boff[2];
#pragma unroll
    for (int q = 0; q < 4; q++) {
        swzA[q] = ((uint32_t)((2 * q + hiA) ^ lsw)) << 4;
        swzB[q] = ((uint32_t)((2 * q + hiB) ^ lsw)) << 4;
    }
#pragma unroll
    for (int f = 0; f < 4; f++)
        aoff[f] = (uint32_t)(wm * 64 + f * 16 + rowA) * 128;
#pragma unroll
    for (int f = 0; f < 2; f++)
        boff[f] = (uint32_t)(wn * 32 + f * 16 + rowB) * 128;

    float acc[4][4][4];
#pragma unroll
    for (int mf = 0; mf < 4; mf++)
#pragma unroll
        for (int nf = 0; nf < 4; nf++)
#pragma unroll
            for (int e = 0; e < 4; e++) acc[mf][nf][e] = 0.0f;

    // A-gen: thread owns row m = tid&127, k-half kh = tid>>7 (32 k values)
    const int am = tid & 127;
    const int kh = tid >> 7;
    const float* aTb = g_aT + m0 + am;
    const float* bTb = g_bT + m0 + am;
    const uint32_t genO = (uint32_t)am * 128;       // A row byte offset
    const uint32_t bstO = (uint32_t)am * 256;       // bst row byte offset
    const uint32_t gsw  = (uint32_t)(am & 7);

    // W cp.async: thread owns weight-row n = tid&127, same k-half split
    const __half* wRow = g_W1t + (size_t)(n0 + am) * KP2H + kh * 32;
    const __half* eRow = g_W1e + (size_t)(n0 + am) * 512 + sp * 64 + kh * 32;
    const uint32_t wO  = (uint32_t)am * 128;

// Fill b-stage for jc: bst[m][j] fp32, group (j>>2) XOR-swizzled by m&7
#define LDBST(jc_) { _Pragma("unroll") \
    for (int it = 0; it < 32; it++) { \
        int idx = tid + it * 256; \
        int j = idx >> 7, mm = idx & 127; \
        float v = __ldg(g_bT + (size_t)((jc_) * 64 + j) * B_SZ + m0 + mm); \
        uint32_t ad = sbst + (uint32_t)mm * 256 + \
                      ((((uint32_t)(j >> 2)) ^ (uint32_t)(mm & 7)) << 4) + (j & 3) * 4; \
        asm volatile("st.shared.f32 [%0], %1;" :: "r"(ad), "f"(v) : "memory"); } }

// A-gen: 8 LDS.128 (b fp32) + mul + pack + 4 STS.128 per thread
#define GENA(buf_, av_) { const float av__ = (av_); _Pragma("unroll") \
    for (int w2 = 0; w2 < 4; w2++) { \
        const uint32_t w = 4u * kh + w2; \
        float4 b0, b1; \
        asm volatile("ld.shared.v4.f32 {%0,%1,%2,%3}, [%4];" \
            : "=f"(b0.x), "=f"(b0.y), "=f"(b0.z), "=f"(b0.w) \
            : "r"(sbst + bstO + (((2u * w) ^ gsw) << 4))); \
        asm volatile("ld.shared.v4.f32 {%0,%1,%2,%3}, [%4];" \
            : "=f"(b1.x), "=f"(b1.y), "=f"(b1.z), "=f"(b1.w) \
            : "r"(sbst + bstO + (((2u * w + 1u) ^ gsw) << 4))); \
        uint32_t p0 = pkh2(av__ * b0.x, av__ * b0.y); \
        uint32_t p1 = pkh2(av__ * b0.z, av__ * b0.w); \
        uint32_t p2 = pkh2(av__ * b1.x, av__ * b1.y); \
        uint32_t p3 = pkh2(av__ * b1.z, av__ * b1.w); \
        asm volatile("st.shared.v4.b32 [%0], {%1,%2,%3,%4};" \
            :: "r"(sA[buf_] + genO + ((w ^ gsw) << 4)), \
               "r"(p0), "r"(p1), "r"(p2), "r"(p3) : "memory"); } }

// Edge-tile A: A[m,e] = a[m,ke] (ke<256), 1 (ke==256), b[m,ke-257] (ke>256)
#define GENE(buf_) { _Pragma("unroll") \
    for (int w2 = 0; w2 < 4; w2++) { \
        const uint32_t w = 4u * kh + w2; \
        float v[8]; \
        _Pragma("unroll") \
        for (int r = 0; r < 8; r++) { \
            const int ke = sp * 64 + (int)w * 8 + r; \
            float x; \
            if (ke < 256)       x = __ldg(aTb + (size_t)ke * B_SZ); \
            else if (ke == 256) x = 1.0f; \
            else                x = __ldg(bTb + (size_t)(ke - 257) * B_SZ); \
            v[r] = x; } \
        uint32_t p0 = pkh2(v[0], v[1]), p1 = pkh2(v[2], v[3]); \
        uint32_t p2 = pkh2(v[4], v[5]), p3 = pkh2(v[6], v[7]); \
        asm volatile("st.shared.v4.b32 [%0], {%1,%2,%3,%4};" \
            :: "r"(sA[buf_] + genO + ((w ^ gsw) << 4)), \
               "r"(p0), "r"(p1), "r"(p2), "r"(p3) : "memory"); } }

#define CPW(buf_, i_, jc_) { const __half* src__ = wRow + (size_t)(i_) * 256 + (jc_) * 64; \
    _Pragma("unroll") \
    for (int w2 = 0; w2 < 4; w2++) \
        cp16(sW[buf_] + wO + (((4u * kh + w2) ^ gsw) << 4), src__ + w2 * 8); \
    asm volatile("cp.async.commit_group;"); }

#define CPWE(buf_) { _Pragma("unroll") \
    for (int w2 = 0; w2 < 4; w2++) \
        cp16(sW[buf_] + wO + (((4u * kh + w2) ^ gsw) << 4), eRow + w2 * 8); \
    asm volatile("cp.async.commit_group;"); }

    // prologue: tile 0 (jc=0, i=i0)
    LDBST(0);
    __syncthreads();
    float av = __ldg(aTb + (size_t)i0 * B_SZ);
    GENA(0, av);
    CPW(0, i0, 0);
    float av_pf = __ldg(aTb + (size_t)(i0 + 1) * B_SZ);

    const int NT = 129;  // 4 jc * 32 i  + 1 edge tile
    for (int T = 0; T < NT; T++) {
        const int buf = T & 1;
        asm volatile("cp.async.wait_group 0;");
        __syncthreads();

        if (T < NT - 1) {
            const int Tn = T + 1;
            if (Tn == 128) {
                GENE(buf ^ 1);
                CPWE(buf ^ 1);
            } else {
                const int jcn = Tn >> 5, iin = Tn & 31;
                if (iin == 0) {
                    LDBST(jcn);
                    __syncthreads();
                }
                GENA(buf ^ 1, av_pf);
                CPW(buf ^ 1, i0 + iin, jcn);
                if (T < 126)
                    av_pf = __ldg(aTb + (size_t)(i0 + ((T + 2) & 31)) * B_SZ);
            }
        }

        // MMA on current buffer: 4 k-steps of 16
#pragma unroll
        for (int q = 0; q < 4; q++) {
            uint32_t afr[4][4], bfr[2][4];
#pragma unroll
            for (int mf = 0; mf < 4; mf++)
                ldsm4(sA[buf] + aoff[mf] + swzA[q], afr[mf]);
#pragma unroll
            for (int n2 = 0; n2 < 2; n2++)
                ldsm4(sW[buf] + boff[n2] + swzB[q], bfr[n2]);
#pragma unroll
            for (int mf = 0; mf < 4; mf++)
#pragma unroll
                for (int nf = 0; nf < 4; nf++)
                    mma_f16(acc[mf][nf], afr[mf], &bfr[nf >> 1][(nf & 1) * 2]);
        }
    }

    // epilogue -> g_part[sp]
    float* base = g_part + (size_t)sp * B_SZ * NN;
#pragma unroll
    for (int mf = 0; mf < 4; mf++) {
        const int gm = m0 + wm * 64 + mf * 16 + (L >> 2);
#pragma unroll
        for (int nf = 0; nf < 4; nf++) {
            const int gn = n0 + wn * 32 + nf * 8 + 2 * (L & 3);
            float2 lo = { acc[mf][nf][0], acc[mf][nf][1] };
            float2 hi = { acc[mf][nf][2], acc[mf][nf][3] };
            *(float2*)(base + (size_t)gm * NN + gn)       = lo;
            *(float2*)(base + (size_t)(gm + 8) * NN + gn) = hi;
        }
    }
}

// ================================================================================
// Reduce 8 partial slots + leftover edge column (ke=512 -> i=256,j=255) + b1 +
// relu -> h (smem), then layer2 FFMA2 + b2 + relu
// ================================================================================
__global__ void __launch_bounds__(256) reduce_l2(
    const float* __restrict__ W1, const float* __restrict__ b1,
    const float* __restrict__ W2, const float* __restrict__ b2,
    float* __restrict__ out) {
    __shared__ float h_t[256 * 34];  // h transposed: h_t[k][m], stride 34
    const int m0 = blockIdx.x * 32;
    const int n  = threadIdx.x;

    const float bb1 = __ldg(b1 + n);
    // leftover edge term: fusion[m, 256*257+255] = b[m,255]; weight row 66047
    const float wlast = __ldg(W1 + (size_t)66047 * NN + n);
#pragma unroll 4
    for (int q = 0; q < 32; q++) {
        const float blast = __ldg(g_bT + (size_t)255 * B_SZ + m0 + q);
        float sum = fmaf(blast, wlast, bb1);
#pragma unroll
        for (int ss = 0; ss < NSLOT; ss++)
            sum += g_part[((size_t)ss * B_SZ + m0 + q) * NN + n];
        h_t[n * 34 + q] = fmaxf(sum, 0.0f);
    }
    __syncthreads();

    unsigned long long acc[16];
#pragma unroll
    for (int mp = 0; mp < 16; mp++) acc[mp] = 0ull;

#pragma unroll 4
    for (int k = 0; k < NN; k++) {
        const unsigned long long wp = pk1(__ldg(W2 + (size_t)k * NN + n));
        const float* hk = &h_t[k * 34];
#pragma unroll
        for (int mp = 0; mp < 16; mp++) {
            unsigned long long hv = *(const unsigned long long*)(hk + 2 * mp);
            acc[mp] = ffma2(hv, wp, acc[mp]);
        }
    }

    const float bb2 = __ldg(b2 + n);
#pragma unroll
    for (int mp = 0; mp < 16; mp++) {
        float x, y;
        upk(acc[mp], x, y);
        out[(size_t)(m0 + 2 * mp) * NN + n]     = fmaxf(x + bb2, 0.0f);
        out[(size_t)(m0 + 2 * mp + 1) * NN + n] = fmaxf(y + bb2, 0.0f);
    }
}

// ================================================================================
extern "C" void kernel_launch(void* const* d_in, const int* in_sizes, int n_in,
                              void* d_out, int out_size) {
    const float* inp1 = (const float*)d_in[0];
    const float* inp2 = (const float*)d_in[1];
    const float* W1   = (const float*)d_in[2];
    const float* b1   = (const float*)d_in[3];
    const float* W2   = (const float*)d_in[4];
    const float* b2   = (const float*)d_in[5];
    float* out = (float*)d_out;

    cudaFuncSetAttribute(mma_main, cudaFuncAttributeMaxDynamicSharedMemorySize, 98304);

    prep_inputs<<<dim3(128, 8, 2), 256>>>(inp1, inp2);
    prep_w1<<<dim3(256, 8, 8), 256>>>(W1);
    prep_w1e<<<dim3(16, 8), 256>>>(W1);
    mma_main<<<dim3(32, 2, NSPLIT), 256, 98304>>>();
    reduce_l2<<<B_SZ / 32, 256>>>(W1, b1, W2, b2, out);
}

// round 10
// speedup vs baseline: 1.3131x; 1.3131x over previous
#include <cuda_runtime.h>
#include <cuda_fp16.h>
#include <cstdint>

#define B_SZ   4096
#define NN     256
#define NA     257
#define KP2H   65536        // W1t row length in halves: 256 i-blocks * 256
#define NPOS   64           // 32 M-blocks x 2 N-blocks
#define TPP    1032         // K-tiles per position: 1024 regular + 8 edge
#define TOTT   (NPOS * TPP) // 66048 total tiles
#define NCTA   296          // 2 per SM, single wave

// ---------------- device-global scratch (no allocation allowed) ----------------
__device__ __align__(256) __half g_W1t[(size_t)NN * KP2H];          // 33.5 MB
__device__ __align__(256) __half g_W1e[(size_t)NN * 512];           // 256 KB edge weights
__device__ __align__(256) float g_aT [(size_t)256 * B_SZ];          // 4 MB
__device__ __align__(256) float g_bT [(size_t)256 * B_SZ];          // 4 MB
__device__ __align__(256) float g_acc[(size_t)B_SZ * NN];           // 4 MB accumulator

// ---------------- helpers ----------------
static __device__ __forceinline__ uint32_t smem_u32(const void* p) {
    uint32_t a;
    asm("{ .reg .u64 t; cvta.to.shared.u64 t, %1; cvt.u32.u64 %0, t; }" : "=r"(a) : "l"(p));
    return a;
}
static __device__ __forceinline__ void cp16(uint32_t s, const void* g) {
    asm volatile("cp.async.cg.shared.global [%0], [%1], 16;" :: "r"(s), "l"(g));
}
// pack (lo,hi) fp32 -> f16x2 (single final rounding, RN)
static __device__ __forceinline__ uint32_t pkh2(float lo, float hi) {
    uint32_t r;
    asm("cvt.rn.f16x2.f32 %0, %1, %2;" : "=r"(r) : "f"(hi), "f"(lo));
    return r;
}
static __device__ __forceinline__ unsigned long long pk1(float x) {
    unsigned long long r;
    asm("mov.b64 %0, {%1, %1};" : "=l"(r) : "f"(x));
    return r;
}
static __device__ __forceinline__ unsigned long long ffma2(
    unsigned long long a, unsigned long long b, unsigned long long c) {
    unsigned long long d;
    asm("fma.rn.f32x2 %0, %1, %2, %3;" : "=l"(d) : "l"(a), "l"(b), "l"(c));
    return d;
}
static __device__ __forceinline__ void upk(unsigned long long v, float& x, float& y) {
    asm("mov.b64 {%0, %1}, %2;" : "=f"(x), "=f"(y) : "l"(v));
}
static __device__ __forceinline__ void ldsm4(uint32_t addr, uint32_t r[4]) {
    asm volatile("ldmatrix.sync.aligned.m8n8.x4.shared.b16 {%0,%1,%2,%3}, [%4];"
                 : "=r"(r[0]), "=r"(r[1]), "=r"(r[2]), "=r"(r[3]) : "r"(addr));
}
static __device__ __forceinline__ void mma_f16(
    float d[4], const uint32_t a[4], const uint32_t b[2]) {
    asm volatile(
        "mma.sync.aligned.m16n8k16.row.col.f32.f16.f16.f32 "
        "{%0,%1,%2,%3}, {%4,%5,%6,%7}, {%8,%9}, {%0,%1,%2,%3};"
        : "+f"(d[0]), "+f"(d[1]), "+f"(d[2]), "+f"(d[3])
        : "r"(a[0]), "r"(a[1]), "r"(a[2]), "r"(a[3]), "r"(b[0]), "r"(b[1]));
}

// ================================================================================
// Pre-pass 0: zero the accumulator (graph-replayed every call)
// ================================================================================
__global__ void __launch_bounds__(256) zero_acc() {
    float4* p = (float4*)g_acc;
    const int idx = blockIdx.x * 256 + threadIdx.x;
#pragma unroll
    for (int q = 0; q < 4; q++)
        p[idx * 4 + q] = make_float4(0.f, 0.f, 0.f, 0.f);
}

// ================================================================================
// Pre-pass 1: transpose inp1 / inp2  ->  g_aT / g_bT  (fp32)
// ================================================================================
__global__ void __launch_bounds__(256) prep_inputs(
    const float* __restrict__ in1, const float* __restrict__ in2) {
    __shared__ float tile[32 * 33];
    const float* src = blockIdx.z ? in2 : in1;
    float* dst = blockIdx.z ? g_bT : g_aT;
    const int m0 = blockIdx.x * 32, c0 = blockIdx.y * 32;
    const int c = threadIdx.x & 31, r0 = threadIdx.x >> 5;
#pragma unroll
    for (int q = 0; q < 4; q++) {
        int r = r0 + q * 8;
        tile[c * 33 + r] = src[(size_t)(m0 + r) * 256 + c0 + c];
    }
    __syncthreads();
#pragma unroll
    for (int q = 0; q < 4; q++) {
        int rr = r0 + q * 8;
        dst[(size_t)(c0 + rr) * B_SZ + m0 + c] = tile[rr * 33 + c];
    }
}

// ================================================================================
// Pre-pass 2: W1t[n][i*256 + j] = fp16(W1[i*257+j][n]),  i<256, j<256
// ================================================================================
__global__ void __launch_bounds__(256) prep_w1(const float* __restrict__ W1) {
    __shared__ float tile[32 * 33];
    const int i = blockIdx.x, j0 = blockIdx.y * 32, n0 = blockIdx.z * 32;
    const int c = threadIdx.x & 31, r0 = threadIdx.x >> 5;
#pragma unroll
    for (int q = 0; q < 4; q++) {
        int jr = r0 + q * 8;
        size_t k = (size_t)i * NA + j0 + jr;
        tile[c * 33 + jr] = W1[k * NN + n0 + c];
    }
    __syncthreads();
#pragma unroll
    for (int q = 0; q < 4; q++) {
        int nr = r0 + q * 8;
        g_W1t[(size_t)(n0 + nr) * KP2H + (size_t)i * 256 + j0 + c] =
            __float2half_rn(tile[nr * 33 + c]);
    }
}

// ================================================================================
// Pre-pass 3: edge weights. ke<257 -> W1 row ke*257+256 ; 257<=ke<512 -> row
// 65792+(ke-257).  g_W1e[n][ke] = fp16(W1[row(ke)][n]).
// ================================================================================
__global__ void __launch_bounds__(256) prep_w1e(const float* __restrict__ W1) {
    __shared__ float tile[32 * 33];
    const int k0 = blockIdx.x * 32, n0 = blockIdx.y * 32;
    const int c = threadIdx.x & 31, r0 = threadIdx.x >> 5;
#pragma unroll
    for (int q = 0; q < 4; q++) {
        int kr = r0 + q * 8;
        int ke = k0 + kr;
        size_t row = (ke < 257) ? ((size_t)ke * NA + 256)
                                : ((size_t)256 * NA + (ke - 257));
        tile[c * 33 + kr] = W1[row * NN + n0 + c];
    }
    __syncthreads();
#pragma unroll
    for (int q = 0; q < 4; q++) {
        int nr = r0 + q * 8;
        g_W1e[(size_t)(n0 + nr) * 512 + k0 + c] = __float2half_rn(tile[nr * 33 + c]);
    }
}

// ================================================================================
// Main: persistent balanced split-K implicit GEMM, mma.sync fp16 m16n8k16.
// 128 threads = 4 warps, warp tile 64x64 (R7 structure). 296 CTAs, each owns
// an even share of the 66048 global K-tiles; position boundary -> RED flush.
// b held as fp16x2 in 32 regs (despill). SMEM 64KB: A0 A1 W0 W1.
// ================================================================================
__global__ void __launch_bounds__(128, 2) mma_main() {
    extern __shared__ __align__(1024) char smem[];
    const uint32_t sbase = smem_u32(smem);
    const uint32_t sA[2] = { sbase,         sbase + 16384 };
    const uint32_t sW[2] = { sbase + 32768, sbase + 49152 };

    const int tid = threadIdx.x;
    const int L   = tid & 31;
    const int wid = tid >> 5;
    const int wm  = wid & 1;    // M half (64 rows)
    const int wn  = wid >> 1;   // N half (64 cols)

    // ldsm lane constants
    const int lsw  = L & 7;
    const int rowA = (L & 7) + ((L >> 3) & 1) * 8;
    const int hiA  = (L >> 4) & 1;
    const int rowB = (L & 7) + ((L >> 4) & 1) * 8;
    const int hiB  = (L >> 3) & 1;
    uint32_t swzA[4], swzB[4], aoff[4], boff[4];
#pragma unroll
    for (int q = 0; q < 4; q++) {
        swzA[q] = ((uint32_t)((2 * q + hiA) ^ lsw)) << 4;
        swzB[q] = ((uint32_t)((2 * q + hiB) ^ lsw)) << 4;
    }
#pragma unroll
    for (int f = 0; f < 4; f++) {
        aoff[f] = (uint32_t)(wm * 64 + f * 16 + rowA) * 128;
        boff[f] = (uint32_t)(wn * 64 + f * 16 + rowB) * 128;
    }

    const uint32_t genO = (uint32_t)tid * 128;
    const uint32_t gsw  = (uint32_t)(tid & 7);
    const uint32_t wO   = (uint32_t)tid * 128;

    float acc[4][8][4];
    uint32_t bregh[32];   // b[myrow][jc*64 .. +63] as fp16x2

    // even share of global tiles
    const int start = (int)(((long long)blockIdx.x * TOTT) / NCTA);
    const int end   = (int)(((long long)(blockIdx.x + 1) * TOTT) / NCTA);

#define LDB(jc_) { _Pragma("unroll") \
    for (int e = 0; e < 32; e++) { \
        float x0 = __ldg(bTb + (size_t)((jc_) * 64 + 2 * e)     * B_SZ); \
        float x1 = __ldg(bTb + (size_t)((jc_) * 64 + 2 * e + 1) * B_SZ); \
        bregh[e] = pkh2(x0, x1); } }

#define GENA(buf_, av_) { const float av__ = (av_); _Pragma("unroll") \
    for (int w = 0; w < 8; w++) { \
        uint32_t p[4]; \
        _Pragma("unroll") \
        for (int u = 0; u < 4; u++) { \
            float2 bf = __half22float2(*(__half2*)&bregh[w * 4 + u]); \
            p[u] = pkh2(av__ * bf.x, av__ * bf.y); } \
        asm volatile("st.shared.v4.b32 [%0], {%1,%2,%3,%4};" \
            :: "r"(sA[buf_] + genO + (((uint32_t)w ^ gsw) << 4)), \
               "r"(p[0]), "r"(p[1]), "r"(p[2]), "r"(p[3]) : "memory"); } }

#define GENE(buf_, et_) { _Pragma("unroll") \
    for (int w = 0; w < 8; w++) { \
        float v[8]; \
        _Pragma("unroll") \
        for (int r = 0; r < 8; r++) { \
            const int ke = (et_) * 64 + w * 8 + r; \
            float x; \
            if (ke < 256)       x = __ldg(aTb + (size_t)ke * B_SZ); \
            else if (ke == 256) x = 1.0f; \
            else                x = __ldg(bTb + (size_t)(ke - 257) * B_SZ); \
            v[r] = x; } \
        uint32_t p0 = pkh2(v[0], v[1]), p1 = pkh2(v[2], v[3]); \
        uint32_t p2 = pkh2(v[4], v[5]), p3 = pkh2(v[6], v[7]); \
        asm volatile("st.shared.v4.b32 [%0], {%1,%2,%3,%4};" \
            :: "r"(sA[buf_] + genO + (((uint32_t)w ^ gsw) << 4)), \
               "r"(p0), "r"(p1), "r"(p2), "r"(p3) : "memory"); } }

#define CPW(buf_, i_, jc_) { const __half* src__ = wRow + (size_t)(i_) * 256 + (jc_) * 64; \
    _Pragma("unroll") \
    for (int w = 0; w < 8; w++) \
        cp16(sW[buf_] + wO + (((uint32_t)w ^ gsw) << 4), src__ + w * 8); \
    asm volatile("cp.async.commit_group;"); }

#define CPWE(buf_, et_) { const __half* src__ = eRow + (et_) * 64; \
    _Pragma("unroll") \
    for (int w = 0; w < 8; w++) \
        cp16(sW[buf_] + wO + (((uint32_t)w ^ gsw) << 4), src__ + w * 8); \
    asm volatile("cp.async.commit_group;"); }

    int t = start;
    while (t < end) {
        const int pos = t / TPP;
        const int pend = (pos + 1) * TPP < end ? (pos + 1) * TPP : end;
        const int ls = t - pos * TPP;
        const int le = pend - pos * TPP;
        const int m0 = (pos >> 1) * 128;
        const int n0 = (pos & 1) * 128;

        const float* aTb = g_aT + m0 + tid;
        const float* bTb = g_bT + m0 + tid;
        const __half* wRow = g_W1t + (size_t)(n0 + tid) * KP2H;
        const __half* eRow = g_W1e + (size_t)(n0 + tid) * 512;

#pragma unroll
        for (int mf = 0; mf < 4; mf++)
#pragma unroll
            for (int nf = 0; nf < 8; nf++)
#pragma unroll
                for (int e = 0; e < 4; e++) acc[mf][nf][e] = 0.0f;

        __syncthreads();  // protect sA[0] from lagging warps of previous segment

        // prologue: tile ls
        int jc_cur = -1;
        if (ls < 1024) {
            jc_cur = ls >> 8;
            LDB(jc_cur);
            float av0 = __ldg(aTb + (size_t)(ls & 255) * B_SZ);
            GENA(0, av0);
            CPW(0, ls & 255, jc_cur);
        } else {
            GENE(0, ls - 1024);
            CPWE(0, ls - 1024);
        }
        float av_pf = 0.0f;
        if (ls + 1 < le && ls + 1 < 1024)
            av_pf = __ldg(aTb + (size_t)((ls + 1) & 255) * B_SZ);

        int buf = 0;
        for (int T = ls; T < le; T++) {
            asm volatile("cp.async.wait_group 0;");
            __syncthreads();

            if (T + 1 < le) {
                const int nt = T + 1;
                if (nt >= 1024) {
                    GENE(buf ^ 1, nt - 1024);
                    CPWE(buf ^ 1, nt - 1024);
                } else {
                    if ((nt >> 8) != jc_cur) { jc_cur = nt >> 8; LDB(jc_cur); }
                    GENA(buf ^ 1, av_pf);
                    CPW(buf ^ 1, nt & 255, jc_cur);
                    if (T + 2 < le && T + 2 < 1024)
                        av_pf = __ldg(aTb + (size_t)((T + 2) & 255) * B_SZ);
                }
            }

            // MMA on current buffer: 4 k-steps of 16
#pragma unroll
            for (int q = 0; q < 4; q++) {
                uint32_t afr[4][4], bfr[4][4];
#pragma unroll
                for (int mf = 0; mf < 4; mf++)
                    ldsm4(sA[buf] + aoff[mf] + swzA[q], afr[mf]);
#pragma unroll
                for (int n2 = 0; n2 < 4; n2++)
                    ldsm4(sW[buf] + boff[n2] + swzB[q], bfr[n2]);
#pragma unroll
                for (int mf = 0; mf < 4; mf++)
#pragma unroll
                    for (int nf = 0; nf < 8; nf++)
                        mma_f16(acc[mf][nf], afr[mf], &bfr[nf >> 1][(nf & 1) * 2]);
            }
            buf ^= 1;
        }

        // flush this position's contribution (RED, no return value used)
#pragma unroll
        for (int mf = 0; mf < 4; mf++) {
            const int gm = m0 + wm * 64 + mf * 16 + (L >> 2);
#pragma unroll
            for (int nf = 0; nf < 8; nf++) {
                const int gn = n0 + wn * 64 + nf * 8 + 2 * (L & 3);
                float* p0 = g_acc + (size_t)gm * NN + gn;
                float* p1 = g_acc + (size_t)(gm + 8) * NN + gn;
                atomicAdd(p0,     acc[mf][nf][0]);
                atomicAdd(p0 + 1, acc[mf][nf][1]);
                atomicAdd(p1,     acc[mf][nf][2]);
                atomicAdd(p1 + 1, acc[mf][nf][3]);
            }
        }

        t = pend;
    }
}

// ================================================================================
// Reduce: g_acc + leftover edge column (ke=512 -> i=256,j=255) + b1 + relu -> h,
// then layer2 FFMA2 + b2 + relu
// ================================================================================
__global__ void __launch_bounds__(256) reduce_l2(
    const float* __restrict__ W1, const float* __restrict__ b1,
    const float* __restrict__ W2, const float* __restrict__ b2,
    float* __restrict__ out) {
    __shared__ float h_t[256 * 34];  // h transposed: h_t[k][m], stride 34
    const int m0 = blockIdx.x * 32;
    const int n  = threadIdx.x;

    const float bb1 = __ldg(b1 + n);
    // leftover edge term: fusion[m, 256*257+255] = b[m,255]; weight row 66047
    const float wlast = __ldg(W1 + (size_t)66047 * NN + n);
#pragma unroll 4
    for (int q = 0; q < 32; q++) {
        const float blast = __ldg(g_bT + (size_t)255 * B_SZ + m0 + q);
        float sum = fmaf(blast, wlast, bb1) + g_acc[(size_t)(m0 + q) * NN + n];
        h_t[n * 34 + q] = fmaxf(sum, 0.0f);
    }
    __syncthreads();

    unsigned long long acc[16];
#pragma unroll
    for (int mp = 0; mp < 16; mp++) acc[mp] = 0ull;

#pragma unroll 4
    for (int k = 0; k < NN; k++) {
        const unsigned long long wp = pk1(__ldg(W2 + (size_t)k * NN + n));
        const float* hk = &h_t[k * 34];
#pragma unroll
        for (int mp = 0; mp < 16; mp++) {
            unsigned long long hv = *(const unsigned long long*)(hk + 2 * mp);
            acc[mp] = ffma2(hv, wp, acc[mp]);
        }
    }

    const float bb2 = __ldg(b2 + n);
#pragma unroll
    for (int mp = 0; mp < 16; mp++) {
        float x, y;
        upk(acc[mp], x, y);
        out[(size_t)(m0 + 2 * mp) * NN + n]     = fmaxf(x + bb2, 0.0f);
        out[(size_t)(m0 + 2 * mp + 1) * NN + n] = fmaxf(y + bb2, 0.0f);
    }
}

// ================================================================================
extern "C" void kernel_launch(void* const* d_in, const int* in_sizes, int n_in,
                              void* d_out, int out_size) {
    const float* inp1 = (const float*)d_in[0];
    const float* inp2 = (const float*)d_in[1];
    const float* W1   = (const float*)d_in[2];
    const float* b1   = (const float*)d_in[3];
    const float* W2   = (const float*)d_in[4];
    const float* b2   = (const float*)d_in[5];
    float* out = (float*)d_out;

    cudaFuncSetAttribute(mma_main, cudaFuncAttributeMaxDynamicSharedMemorySize, 65536);

    zero_acc<<<B_SZ * NN / (256 * 16), 256>>>();
    prep_inputs<<<dim3(128, 8, 2), 256>>>(inp1, inp2);
    prep_w1<<<dim3(256, 8, 8), 256>>>(W1);
    prep_w1e<<<dim3(16, 8), 256>>>(W1);
    mma_main<<<NCTA, 128, 65536>>>();
    reduce_l2<<<B_SZ / 32, 256>>>(W1, b1, W2, b2, out);
}